// round 16
// baseline (speedup 1.0000x reference)
#include <cuda_runtime.h>
#include <cstdint>

typedef unsigned long long ull;

#define NROWS 8192
#define DDIM 1024
#define KCLS 80
#define KP1 81
#define MCAND 2048
#define NTOPK 100
#define CAP 65536
#define SCORE_T 0.05f
#define NMS_T 0.5f
#define IMG_H 800.0f
#define IMG_W 1216.0f
#define SCALE_CLAMP 4.135166556742356f

// ---------------- scratch (static device globals; no allocation) -------------
__device__ int g_count;                 // reset by k_nms_out (after last use)
__device__ ull g_keys[CAP];
__device__ ull g_keys2[32768];
__device__ float g_probs[NROWS * KCLS];
__device__ unsigned g_flag1[32];        // phase-1 done flags (reset by k_topk)
__device__ unsigned g_flag2[8];         // phase-2 done flags (reset by k_topk)
__device__ float4 g_box[MCAND];
__device__ int   g_cls[MCAND];
__device__ float g_score[MCAND];
__device__ unsigned g_validw[64];
__device__ unsigned g_rowNZ[64];
__device__ unsigned g_mask[MCAND * 64];

// ---------------- packed f32x2 helpers (sm_103a) -----------------------------
__device__ __forceinline__ ull pack2(float lo, float hi) {
    ull r; asm("mov.b64 %0,{%1,%2};" : "=l"(r) : "f"(lo), "f"(hi)); return r;
}
__device__ __forceinline__ void unpack2(ull v, float& lo, float& hi) {
    asm("mov.b64 {%0,%1},%2;" : "=f"(lo), "=f"(hi) : "l"(v));
}
__device__ __forceinline__ ull ffma2(ull a, ull b, ull c) {
    ull d; asm("fma.rn.f32x2 %0,%1,%2,%3;" : "=l"(d) : "l"(a), "l"(b), "l"(c));
    return d;
}

// ---------------- cls GEMM + softmax + candidate append ---------------------
// BM=64 rows x 96 cols (81 real), BK=32, 384 threads (12 warps -> 3/SMSP),
// grid 128. Thread tile 4 rows x 4 cols; FFMA2; LDS.128 for x and w.
#define BM 64
#define BK 32
#define XST 68   // 272B rows: 16B-aligned for LDS.128

__global__ void __launch_bounds__(384) k_gemm_softmax(
    const float* __restrict__ x, const float* __restrict__ cw,
    const float* __restrict__ cb)
{
    __shared__ float xs[2][BK][XST];   // [buf][k][m]
    __shared__ float ws[2][BK][96];    // [buf][k][c]; reused as 64x96 logits
    int t = threadIdx.x;
    int tx = t >> 4;                   // 0..23: 4 cols each
    int ty = t & 15;                   // 0..15: 4 rows each
    int m0 = blockIdx.x * BM;

    ull acc[4][2];
#pragma unroll
    for (int i = 0; i < 4; i++) { acc[i][0] = 0ULL; acc[i][1] = 0ULL; }

    float4 xr0, xr1;
    float wr[8];

    // prologue: global->reg for tile 0
    {
        int f = t & 7, m = t >> 3;
        xr0 = *(const float4*)(x + (size_t)(m0 + m) * DDIM + f * 4);
        if (t < 128) {
            int i1 = 384 + t; int f1 = i1 & 7, m1 = i1 >> 3;
            xr1 = *(const float4*)(x + (size_t)(m0 + m1) * DDIM + f1 * 4);
        }
    }
#pragma unroll
    for (int q = 0; q < 8; q++) {
        int idx = q * 384 + t; int kk = idx / 96; int c = idx - kk * 96;
        wr[q] = (c < KP1) ? cw[(size_t)kk * KP1 + c] : 0.f;
    }
    // reg->smem buf 0
    {
        int f = t & 7, m = t >> 3;
        xs[0][f * 4 + 0][m] = xr0.x; xs[0][f * 4 + 1][m] = xr0.y;
        xs[0][f * 4 + 2][m] = xr0.z; xs[0][f * 4 + 3][m] = xr0.w;
        if (t < 128) {
            int i1 = 384 + t; int f1 = i1 & 7, m1 = i1 >> 3;
            xs[0][f1 * 4 + 0][m1] = xr1.x; xs[0][f1 * 4 + 1][m1] = xr1.y;
            xs[0][f1 * 4 + 2][m1] = xr1.z; xs[0][f1 * 4 + 3][m1] = xr1.w;
        }
    }
#pragma unroll
    for (int q = 0; q < 8; q++) {
        int idx = q * 384 + t; int kk = idx / 96; int c = idx - kk * 96;
        ws[0][kk][c] = wr[q];
    }
    __syncthreads();

    for (int tile = 0; tile < DDIM / BK; tile++) {
        int cur = tile & 1;
        if (tile < DDIM / BK - 1) {
            int kc = (tile + 1) * BK;
            int f = t & 7, m = t >> 3;
            xr0 = *(const float4*)(x + (size_t)(m0 + m) * DDIM + kc + f * 4);
            if (t < 128) {
                int i1 = 384 + t; int f1 = i1 & 7, m1 = i1 >> 3;
                xr1 = *(const float4*)(x + (size_t)(m0 + m1) * DDIM + kc + f1 * 4);
            }
#pragma unroll
            for (int q = 0; q < 8; q++) {
                int idx = q * 384 + t; int kk = idx / 96; int c = idx - kk * 96;
                wr[q] = (c < KP1) ? cw[(size_t)(kc + kk) * KP1 + c] : 0.f;
            }
        }
#pragma unroll 8
        for (int kk = 0; kk < BK; kk++) {
            ulonglong2 wv = *(const ulonglong2*)&ws[cur][kk][tx * 4];  // LDS.128
            float4 xv = *(const float4*)&xs[cur][kk][ty * 4];          // LDS.128
            ull xd0 = pack2(xv.x, xv.x);
            ull xd1 = pack2(xv.y, xv.y);
            ull xd2 = pack2(xv.z, xv.z);
            ull xd3 = pack2(xv.w, xv.w);
            acc[0][0] = ffma2(xd0, wv.x, acc[0][0]);
            acc[0][1] = ffma2(xd0, wv.y, acc[0][1]);
            acc[1][0] = ffma2(xd1, wv.x, acc[1][0]);
            acc[1][1] = ffma2(xd1, wv.y, acc[1][1]);
            acc[2][0] = ffma2(xd2, wv.x, acc[2][0]);
            acc[2][1] = ffma2(xd2, wv.y, acc[2][1]);
            acc[3][0] = ffma2(xd3, wv.x, acc[3][0]);
            acc[3][1] = ffma2(xd3, wv.y, acc[3][1]);
        }
        if (tile < DDIM / BK - 1) {
            int nb = cur ^ 1;
            int f = t & 7, m = t >> 3;
            xs[nb][f * 4 + 0][m] = xr0.x; xs[nb][f * 4 + 1][m] = xr0.y;
            xs[nb][f * 4 + 2][m] = xr0.z; xs[nb][f * 4 + 3][m] = xr0.w;
            if (t < 128) {
                int i1 = 384 + t; int f1 = i1 & 7, m1 = i1 >> 3;
                xs[nb][f1 * 4 + 0][m1] = xr1.x; xs[nb][f1 * 4 + 1][m1] = xr1.y;
                xs[nb][f1 * 4 + 2][m1] = xr1.z; xs[nb][f1 * 4 + 3][m1] = xr1.w;
            }
#pragma unroll
            for (int q = 0; q < 8; q++) {
                int idx = q * 384 + t; int kk = idx / 96; int c = idx - kk * 96;
                ws[nb][kk][c] = wr[q];
            }
        }
        __syncthreads();
    }

    // epilogue A: biased logits -> smem L (reuse ws: 2*32*96 = 64*96)
    float* L = &ws[0][0][0];
#pragma unroll
    for (int i = 0; i < 4; i++) {
        float l0, l1, l2, l3;
        unpack2(acc[i][0], l0, l1);
        unpack2(acc[i][1], l2, l3);
        float lv[4] = {l0, l1, l2, l3};
#pragma unroll
        for (int j = 0; j < 4; j++) {
            int c = tx * 4 + j;
            L[(ty * 4 + i) * 96 + c] = (c < KP1) ? lv[j] + cb[c] : -1e30f;
        }
    }
    __syncthreads();

    // epilogue B: warp-per-row softmax + candidate append (12 warps, 64 rows)
    int wid = t >> 5, lane = t & 31;
    for (int r = wid; r < BM; r += 12) {
        float v0 = L[r * 96 + lane];
        float v1 = L[r * 96 + lane + 32];
        float v2 = L[r * 96 + lane + 64];
        float mx = fmaxf(v0, fmaxf(v1, v2));
#pragma unroll
        for (int o = 16; o >= 1; o >>= 1)
            mx = fmaxf(mx, __shfl_xor_sync(0xffffffffu, mx, o));
        float e0 = expf(v0 - mx), e1 = expf(v1 - mx), e2 = expf(v2 - mx);
        float sm = e0 + e1 + e2;
#pragma unroll
        for (int o = 16; o >= 1; o >>= 1)
            sm += __shfl_xor_sync(0xffffffffu, sm, o);
        float inv = 1.0f / sm;
        int rg = m0 + r;
        float ev[3] = {e0, e1, e2};
#pragma unroll
        for (int q = 0; q < 3; q++) {
            int c = lane + q * 32;
            float p = ev[q] * inv;
            bool isr = (c < KCLS);
            if (isr) g_probs[(size_t)rg * KCLS + c] = p;
            bool cond = isr && (p > SCORE_T);
            unsigned msk = __ballot_sync(0xffffffffu, cond);
            if (cond) {
                int leader = __ffs(msk) - 1;
                int rank = __popc(msk & ((1u << lane) - 1));
                int base = 0;
                if (lane == leader) base = atomicAdd(&g_count, __popc(msk));
                base = __shfl_sync(msk, base, leader);
                int pos = base + rank;
                if (pos < CAP) {
                    unsigned vb = __float_as_uint(p);
                    g_keys[pos] = ((ull)(~vb) << 32) | (unsigned)(rg * KCLS + c);
                }
            }
        }
    }
}

// --------- helper: fold one sorted list into sA (partner-min + merge) -------
__device__ __forceinline__ void fold_into(ull* sA, ull* sC,
                                          const ull* __restrict__ src) {
    int t = threadIdx.x;
    sC[t] = src[t]; sC[t + 1024] = src[t + 1024];
    __syncthreads();
#pragma unroll
    for (int q = 0; q < 2; q++) {
        int i = t + q * 1024;
        ull a = sA[i], c = sC[2047 - i];
        sA[i] = a < c ? a : c;
    }
    __syncthreads();
    for (int j = 1024; j > 0; j >>= 1) {
        int i = ((t & ~(j - 1)) << 1) | (t & (j - 1));
        ull a = sA[i], c = sA[i + j];
        if (a > c) { sA[i] = c; sA[i + j] = a; }
        __syncthreads();
    }
}

// ------ fused top-2048: sort chunks + 2 fold rounds in ONE kernel -----------
// 32 blocks (all co-resident on 148 SMs -> spin-wait safe).
// Phase 1: block b sorts chunk b (count-aware), sets g_flag1[b].
// Phase 2: blocks 0..7 wait on ACTIVE input flags, fold 4 lists -> g_keys2,
//          set g_flag2[b].
// Phase 3: block 0 waits on active g_flag2, folds up to 8 lists -> g_keys,
//          zeroes flags/validw/rowNZ, tail-fills if cnt < 2048.
// Flag protocol: writer __threadfence() then atomicExch; reader polls
// atomicAdd(flag,0), then __syncthreads before touching data (canonical
// threadFenceReduction pattern). Exactness of folds proven in prior rounds.
__global__ void __launch_bounds__(1024) k_topk() {
    __shared__ ull sA[2048], sC[2048];
    int t = threadIdx.x, b = blockIdx.x;
    int cnt = min(g_count, CAP);

    // ---- Phase 1: sort chunk b ----
    int base = b * 2048;
    if (base < cnt) {
        ull* src = g_keys + base;
        sA[t] = (base + t < cnt) ? src[t] : ~0ULL;
        sA[t + 1024] = (base + t + 1024 < cnt) ? src[t + 1024] : ~0ULL;
        __syncthreads();
        for (unsigned k = 2; k <= 2048; k <<= 1) {
            for (unsigned j = k >> 1; j > 0; j >>= 1) {
#pragma unroll
                for (int q = 0; q < 2; q++) {
                    unsigned i = t + q * 1024;
                    unsigned ixj = i ^ j;
                    if (ixj > i) {
                        bool up = ((i & k) == 0);
                        ull a = sA[i], c = sA[ixj];
                        if ((a > c) == up) { sA[i] = c; sA[ixj] = a; }
                    }
                }
                __syncthreads();
            }
        }
        src[t] = sA[t];
        src[t + 1024] = sA[t + 1024];
    }
    __syncthreads();
    if (t == 0) { __threadfence(); atomicExch(&g_flag1[b], 1u); }
    if (b >= 8) return;

    // ---- Phase 2: fold chunks 4b..4b+3 -> g_keys2 + b*2048 ----
    int c0 = 4 * b;
    bool act2 = ((size_t)c0 * 2048 < (size_t)cnt);
    if (act2) {
        int nact = 0;
        for (int i = 0; i < 4; i++)
            if ((size_t)(c0 + i) * 2048 < (size_t)cnt) nact = i + 1;
        if (t == 0)
            for (int i = 0; i < nact; i++)
                while (atomicAdd(&g_flag1[c0 + i], 0u) == 0u) {}
        __syncthreads();
        sA[t] = g_keys[(size_t)c0 * 2048 + t];
        sA[t + 1024] = g_keys[(size_t)c0 * 2048 + t + 1024];
        __syncthreads();
        for (int i = 1; i < nact; i++)
            fold_into(sA, sC, g_keys + (size_t)(c0 + i) * 2048);
        g_keys2[(size_t)b * 2048 + t] = sA[t];
        g_keys2[(size_t)b * 2048 + t + 1024] = sA[t + 1024];
    }
    __syncthreads();
    if (t == 0) { __threadfence(); atomicExch(&g_flag2[b], 1u); }
    if (b != 0) return;

    // ---- Phase 3: fold up to 8 lists from g_keys2 -> g_keys[0..2047] ----
    {
        int nact = 0;
        for (int i = 0; i < 8; i++)
            if ((size_t)i * 8192 < (size_t)cnt) nact = i + 1;
        if (t == 0)
            for (int i = 0; i < nact; i++)
                while (atomicAdd(&g_flag2[i], 0u) == 0u) {}
        __syncthreads();
        if (nact > 0) {
            sA[t] = g_keys2[t];
            sA[t + 1024] = g_keys2[t + 1024];
            __syncthreads();
            for (int i = 1; i < nact; i++)
                fold_into(sA, sC, g_keys2 + (size_t)i * 2048);
        } else {
            sA[t] = ~0ULL; sA[t + 1024] = ~0ULL;
            __syncthreads();
        }
        g_keys[t] = sA[t];
        g_keys[t + 1024] = sA[t + 1024];
    }
    // flags reset (all consumers done), downstream flag init, tail fill
    if (t < 32) g_flag1[t] = 0;
    if (t < 8) g_flag2[t] = 0;
    if (t < 64) { g_validw[t] = 0; g_rowNZ[t] = 0; }
    __syncthreads();
    if (t == 0 && cnt < MCAND) {
        int slot = cnt;
        for (int idx = 0; idx < NROWS * KCLS && slot < MCAND; idx++)
            if (!(g_probs[idx] > SCORE_T))
                g_keys[slot++] = (0xFFFFFFFFull << 32) | (unsigned)idx;
    }
}

// ---------------- bbox delta + decode + clip (warp per candidate) -----------
__global__ void __launch_bounds__(256) k_decode(
    const float* __restrict__ x, const float* __restrict__ bw,
    const float* __restrict__ bb, const float* __restrict__ props)
{
    int t = threadIdx.x, lane = t & 31, wid = t >> 5;
    int m = blockIdx.x * 8 + wid;
    ull key = g_keys[m];               // final list lives in g_keys
    unsigned hi = (unsigned)(key >> 32);
    unsigned idx = (unsigned)key;
    if (idx >= (unsigned)(NROWS * KCLS)) idx = 0;   // defensive
    float score = (hi == 0xFFFFFFFFu) ? -1.0f : __uint_as_float(~hi);
    int prop = idx / KCLS, cls = idx - prop * KCLS;

    const float4* x4 = (const float4*)(x + (size_t)prop * DDIM);
    const float4* wr = (const float4*)bw;   // [k][80] float4s
    float a0 = 0, a1 = 0, a2 = 0, a3 = 0;
#pragma unroll 4
    for (int k = lane; k < DDIM / 4; k += 32) {
        float4 xv = __ldg(x4 + k);
        float4 w0 = __ldg(wr + (size_t)(4 * k + 0) * KCLS + cls);
        float4 w1 = __ldg(wr + (size_t)(4 * k + 1) * KCLS + cls);
        float4 w2 = __ldg(wr + (size_t)(4 * k + 2) * KCLS + cls);
        float4 w3 = __ldg(wr + (size_t)(4 * k + 3) * KCLS + cls);
        a0 = fmaf(xv.x, w0.x, fmaf(xv.y, w1.x, fmaf(xv.z, w2.x, fmaf(xv.w, w3.x, a0))));
        a1 = fmaf(xv.x, w0.y, fmaf(xv.y, w1.y, fmaf(xv.z, w2.y, fmaf(xv.w, w3.y, a1))));
        a2 = fmaf(xv.x, w0.z, fmaf(xv.y, w1.z, fmaf(xv.z, w2.z, fmaf(xv.w, w3.z, a2))));
        a3 = fmaf(xv.x, w0.w, fmaf(xv.y, w1.w, fmaf(xv.z, w2.w, fmaf(xv.w, w3.w, a3))));
    }
#pragma unroll
    for (int o = 16; o >= 1; o >>= 1) {
        a0 += __shfl_xor_sync(0xffffffffu, a0, o);
        a1 += __shfl_xor_sync(0xffffffffu, a1, o);
        a2 += __shfl_xor_sync(0xffffffffu, a2, o);
        a3 += __shfl_xor_sync(0xffffffffu, a3, o);
    }
    if (lane == 0) {
        float d0 = a0 + bb[cls * 4 + 0], d1 = a1 + bb[cls * 4 + 1];
        float d2 = a2 + bb[cls * 4 + 2], d3 = a3 + bb[cls * 4 + 3];
        float px1 = props[prop * 4 + 0], py1 = props[prop * 4 + 1];
        float px2 = props[prop * 4 + 2], py2 = props[prop * 4 + 3];
        float w = px2 - px1, h = py2 - py1;
        float cx = px1 + 0.5f * w, cy = py1 + 0.5f * h;
        float dx = d0 / 10.0f, dy = d1 / 10.0f;
        float dw = fminf(d2 / 5.0f, SCALE_CLAMP), dh = fminf(d3 / 5.0f, SCALE_CLAMP);
        float pcx = dx * w + cx, pcy = dy * h + cy;
        float pw = expf(dw) * w, ph = expf(dh) * h;
        float x1 = pcx - 0.5f * pw, y1 = pcy - 0.5f * ph;
        float x2 = pcx + 0.5f * pw, y2 = pcy + 0.5f * ph;
        x1 = fminf(fmaxf(x1, 0.f), IMG_W); y1 = fminf(fmaxf(y1, 0.f), IMG_H);
        x2 = fminf(fmaxf(x2, 0.f), IMG_W); y2 = fminf(fmaxf(y2, 0.f), IMG_H);
        g_box[m] = make_float4(x1, y1, x2, y2);
        g_cls[m] = cls;
        g_score[m] = score;
        if (score > SCORE_T) atomicOr(&g_validw[m >> 5], 1u << (m & 31));
    }
}

// ---------------- suppression mask + nonzero-row bitmap ---------------------
// Reference's class offsets separate classes by > MAX_COORD, so IoU>0 iff same
// class: bit = (j>i) && same class && IoU>NMS_T. Invalid rows never suppress.
__global__ void __launch_bounds__(512) k_mask() {
    __shared__ float4 sb[MCAND];
    __shared__ int scl[MCAND];
    int t = threadIdx.x;
    for (int i = t; i < MCAND; i += 512) { sb[i] = g_box[i]; scl[i] = g_cls[i]; }
    __syncthreads();
    int wid = t >> 5, lane = t & 31;
    int r = blockIdx.x * 16 + wid;
    if (!((g_validw[r >> 5] >> (r & 31)) & 1u)) return;
    float4 rb = sb[r];
    int rc = scl[r];
    float ra = (rb.z - rb.x) * (rb.w - rb.y);
    unsigned anyw = 0;
    for (int w = 0; w < 64; w++) {
        int j = w * 32 + lane;
        float4 jb = sb[j];
        float xx1 = fmaxf(rb.x, jb.x), yy1 = fmaxf(rb.y, jb.y);
        float xx2 = fminf(rb.z, jb.z), yy2 = fminf(rb.w, jb.w);
        float inter = fmaxf(xx2 - xx1, 0.f) * fmaxf(yy2 - yy1, 0.f);
        float ja = (jb.z - jb.x) * (jb.w - jb.y);
        float iou = inter / fmaxf(ra + ja - inter, 1e-9f);
        bool bit = (j > r) && (scl[j] == rc) && (iou > NMS_T);
        unsigned word = __ballot_sync(0xffffffffu, bit);
        if (lane == 0) { g_mask[(size_t)r * 64 + w] = word; anyw |= word; }
    }
    if (lane == 0 && anyw) atomicOr(&g_rowNZ[r >> 5], 1u << (r & 31));
}

// --------- NMS via Jacobi fixpoint (exact: mask is strictly triangular) -----
__global__ void __launch_bounds__(1024) k_nms_out(float* __restrict__ out) {
    __shared__ unsigned Rcur[64], contrib[64], sval[64], nzw[64];
    __shared__ unsigned racc[16][64];
    __shared__ int s_changed;
    __shared__ int kscan[65];
    __shared__ int fidx[NTOPK];
    int t = threadIdx.x;
    if (t == 0) g_count = 0;           // reset for next replay (after last use)
    if (t < 64) { Rcur[t] = 0; sval[t] = g_validw[t]; nzw[t] = g_rowNZ[t]; }
    __syncthreads();
    int w = t & 63, g = t >> 6;
    unsigned gm = (0x00010001u << g);
    for (int iter = 0; iter < MCAND; iter++) {
        if (t < 64) contrib[t] = sval[t] & ~Rcur[t] & nzw[t];
        if (t == 0) s_changed = 0;
        __syncthreads();
        unsigned acc = 0;
        for (int rw = 0; rw < 64; rw++) {
            unsigned bits = contrib[rw] & gm;
            while (bits) {
                int b = __ffs(bits) - 1; bits &= bits - 1;
                acc |= g_mask[(size_t)(rw * 32 + b) * 64 + w];
            }
        }
        racc[g][w] = acc;
        __syncthreads();
        if (t < 64) {
            unsigned a = 0;
#pragma unroll
            for (int q = 0; q < 16; q++) a |= racc[q][t];
            if (a != Rcur[t]) s_changed = 1;
            Rcur[t] = a;
        }
        __syncthreads();
        if (!s_changed) break;
    }
    if (t < 64) sval[t] = sval[t] & ~Rcur[t];
    __syncthreads();
    if (t == 0) {
        int run = 0;
        for (int ww = 0; ww < 64; ww++) { kscan[ww] = run; run += __popc(sval[ww]); }
        kscan[64] = run;
    }
    __syncthreads();
    int KC = kscan[64];
    for (int i = t; i < MCAND; i += 1024) {
        int ww = i >> 5, b = i & 31;
        unsigned kw = sval[ww];
        bool kp = (kw >> b) & 1u;
        int kr = kscan[ww] + __popc(kw & ((1u << b) - 1));
        int slot = kp ? kr : (KC + i - kr);
        if (slot < NTOPK) fidx[slot] = i;
    }
    __syncthreads();
    if (t < NTOPK) {
        int i = fidx[t];
        bool kp = (sval[i >> 5] >> (i & 31)) & 1u;
        float4 b4 = g_box[i];
        out[t * 4 + 0] = b4.x;
        out[t * 4 + 1] = b4.y;
        out[t * 4 + 2] = b4.z;
        out[t * 4 + 3] = b4.w;
        out[400 + t] = kp ? g_score[i] : -1.0f;
        out[500 + t] = (float)g_cls[i];
        out[600 + t] = kp ? 1.0f : 0.0f;
    }
}

// ---------------- launch ----------------------------------------------------
extern "C" void kernel_launch(void* const* d_in, const int* in_sizes, int n_in,
                              void* d_out, int out_size) {
    (void)in_sizes; (void)n_in; (void)out_size;
    const float* x     = (const float*)d_in[0];
    const float* cw    = (const float*)d_in[1];
    const float* cb    = (const float*)d_in[2];
    const float* bw    = (const float*)d_in[3];
    const float* bb    = (const float*)d_in[4];
    const float* props = (const float*)d_in[5];
    float* out = (float*)d_out;

    k_gemm_softmax<<<NROWS / BM, 384>>>(x, cw, cb);
    k_topk<<<32, 1024>>>();            // fused sort + 2 fold rounds
    k_decode<<<MCAND / 8, 256>>>(x, bw, bb, props);
    k_mask<<<MCAND / 16, 512>>>();
    k_nms_out<<<1, 1024>>>(out);
}

// round 17
// speedup vs baseline: 1.1053x; 1.1053x over previous
#include <cuda_runtime.h>
#include <cstdint>

typedef unsigned long long ull;

#define NROWS 8192
#define DDIM 1024
#define KCLS 80
#define KP1 81
#define MCAND 2048
#define NTOPK 100
#define CAP 65536
#define SCORE_T 0.05f
#define NMS_T 0.5f
#define IMG_H 800.0f
#define IMG_W 1216.0f
#define SCALE_CLAMP 4.135166556742356f

// ---------------- scratch (static device globals; no allocation) -------------
__device__ int g_count;                 // reset by k_nms_out (after last use)
__device__ ull g_keys[CAP];
__device__ ull g_keys2[32768];
__device__ float g_probs[NROWS * KCLS];
__device__ unsigned g_flag1[32];        // phase-1 done flags (reset by k_topk)
__device__ unsigned g_flag2[8];         // phase-2 done flags (reset by k_topk)
__device__ float4 g_box[MCAND];
__device__ int   g_cls[MCAND];
__device__ float g_score[MCAND];
__device__ int   g_clsCnt[KCLS];        // class bucket counts (reset by k_nms_out)
__device__ int   g_bucket[KCLS * MCAND];
__device__ unsigned g_validw[64];
__device__ unsigned g_rowNZ[64];
__device__ unsigned g_mask[MCAND * 64];

// ---------------- packed f32x2 helpers (sm_103a) -----------------------------
__device__ __forceinline__ ull pack2(float lo, float hi) {
    ull r; asm("mov.b64 %0,{%1,%2};" : "=l"(r) : "f"(lo), "f"(hi)); return r;
}
__device__ __forceinline__ void unpack2(ull v, float& lo, float& hi) {
    asm("mov.b64 {%0,%1},%2;" : "=f"(lo), "=f"(hi) : "l"(v));
}
__device__ __forceinline__ ull ffma2(ull a, ull b, ull c) {
    ull d; asm("fma.rn.f32x2 %0,%1,%2,%3;" : "=l"(d) : "l"(a), "l"(b), "l"(c));
    return d;
}

// ---------------- cls GEMM + softmax + candidate append ---------------------
// BM=64 rows x 96 cols (81 real), BK=32, 384 threads (12 warps -> 3/SMSP),
// grid 128. Thread tile 4 rows x 4 cols; FFMA2; LDS.128 for x and w.
#define BM 64
#define BK 32
#define XST 68   // 272B rows: 16B-aligned for LDS.128

__global__ void __launch_bounds__(384) k_gemm_softmax(
    const float* __restrict__ x, const float* __restrict__ cw,
    const float* __restrict__ cb)
{
    __shared__ float xs[2][BK][XST];   // [buf][k][m]
    __shared__ float ws[2][BK][96];    // [buf][k][c]; reused as 64x96 logits
    int t = threadIdx.x;
    int tx = t >> 4;                   // 0..23: 4 cols each
    int ty = t & 15;                   // 0..15: 4 rows each
    int m0 = blockIdx.x * BM;

    ull acc[4][2];
#pragma unroll
    for (int i = 0; i < 4; i++) { acc[i][0] = 0ULL; acc[i][1] = 0ULL; }

    float4 xr0, xr1;
    float wr[8];

    // prologue: global->reg for tile 0
    {
        int f = t & 7, m = t >> 3;
        xr0 = *(const float4*)(x + (size_t)(m0 + m) * DDIM + f * 4);
        if (t < 128) {
            int i1 = 384 + t; int f1 = i1 & 7, m1 = i1 >> 3;
            xr1 = *(const float4*)(x + (size_t)(m0 + m1) * DDIM + f1 * 4);
        }
    }
#pragma unroll
    for (int q = 0; q < 8; q++) {
        int idx = q * 384 + t; int kk = idx / 96; int c = idx - kk * 96;
        wr[q] = (c < KP1) ? cw[(size_t)kk * KP1 + c] : 0.f;
    }
    // reg->smem buf 0
    {
        int f = t & 7, m = t >> 3;
        xs[0][f * 4 + 0][m] = xr0.x; xs[0][f * 4 + 1][m] = xr0.y;
        xs[0][f * 4 + 2][m] = xr0.z; xs[0][f * 4 + 3][m] = xr0.w;
        if (t < 128) {
            int i1 = 384 + t; int f1 = i1 & 7, m1 = i1 >> 3;
            xs[0][f1 * 4 + 0][m1] = xr1.x; xs[0][f1 * 4 + 1][m1] = xr1.y;
            xs[0][f1 * 4 + 2][m1] = xr1.z; xs[0][f1 * 4 + 3][m1] = xr1.w;
        }
    }
#pragma unroll
    for (int q = 0; q < 8; q++) {
        int idx = q * 384 + t; int kk = idx / 96; int c = idx - kk * 96;
        ws[0][kk][c] = wr[q];
    }
    __syncthreads();

    for (int tile = 0; tile < DDIM / BK; tile++) {
        int cur = tile & 1;
        if (tile < DDIM / BK - 1) {
            int kc = (tile + 1) * BK;
            int f = t & 7, m = t >> 3;
            xr0 = *(const float4*)(x + (size_t)(m0 + m) * DDIM + kc + f * 4);
            if (t < 128) {
                int i1 = 384 + t; int f1 = i1 & 7, m1 = i1 >> 3;
                xr1 = *(const float4*)(x + (size_t)(m0 + m1) * DDIM + kc + f1 * 4);
            }
#pragma unroll
            for (int q = 0; q < 8; q++) {
                int idx = q * 384 + t; int kk = idx / 96; int c = idx - kk * 96;
                wr[q] = (c < KP1) ? cw[(size_t)(kc + kk) * KP1 + c] : 0.f;
            }
        }
#pragma unroll 8
        for (int kk = 0; kk < BK; kk++) {
            ulonglong2 wv = *(const ulonglong2*)&ws[cur][kk][tx * 4];  // LDS.128
            float4 xv = *(const float4*)&xs[cur][kk][ty * 4];          // LDS.128
            ull xd0 = pack2(xv.x, xv.x);
            ull xd1 = pack2(xv.y, xv.y);
            ull xd2 = pack2(xv.z, xv.z);
            ull xd3 = pack2(xv.w, xv.w);
            acc[0][0] = ffma2(xd0, wv.x, acc[0][0]);
            acc[0][1] = ffma2(xd0, wv.y, acc[0][1]);
            acc[1][0] = ffma2(xd1, wv.x, acc[1][0]);
            acc[1][1] = ffma2(xd1, wv.y, acc[1][1]);
            acc[2][0] = ffma2(xd2, wv.x, acc[2][0]);
            acc[2][1] = ffma2(xd2, wv.y, acc[2][1]);
            acc[3][0] = ffma2(xd3, wv.x, acc[3][0]);
            acc[3][1] = ffma2(xd3, wv.y, acc[3][1]);
        }
        if (tile < DDIM / BK - 1) {
            int nb = cur ^ 1;
            int f = t & 7, m = t >> 3;
            xs[nb][f * 4 + 0][m] = xr0.x; xs[nb][f * 4 + 1][m] = xr0.y;
            xs[nb][f * 4 + 2][m] = xr0.z; xs[nb][f * 4 + 3][m] = xr0.w;
            if (t < 128) {
                int i1 = 384 + t; int f1 = i1 & 7, m1 = i1 >> 3;
                xs[nb][f1 * 4 + 0][m1] = xr1.x; xs[nb][f1 * 4 + 1][m1] = xr1.y;
                xs[nb][f1 * 4 + 2][m1] = xr1.z; xs[nb][f1 * 4 + 3][m1] = xr1.w;
            }
#pragma unroll
            for (int q = 0; q < 8; q++) {
                int idx = q * 384 + t; int kk = idx / 96; int c = idx - kk * 96;
                ws[nb][kk][c] = wr[q];
            }
        }
        __syncthreads();
    }

    // epilogue A: biased logits -> smem L (reuse ws: 2*32*96 = 64*96)
    float* L = &ws[0][0][0];
#pragma unroll
    for (int i = 0; i < 4; i++) {
        float l0, l1, l2, l3;
        unpack2(acc[i][0], l0, l1);
        unpack2(acc[i][1], l2, l3);
        float lv[4] = {l0, l1, l2, l3};
#pragma unroll
        for (int j = 0; j < 4; j++) {
            int c = tx * 4 + j;
            L[(ty * 4 + i) * 96 + c] = (c < KP1) ? lv[j] + cb[c] : -1e30f;
        }
    }
    __syncthreads();

    // epilogue B: warp-per-row softmax + candidate append (12 warps, 64 rows)
    int wid = t >> 5, lane = t & 31;
    for (int r = wid; r < BM; r += 12) {
        float v0 = L[r * 96 + lane];
        float v1 = L[r * 96 + lane + 32];
        float v2 = L[r * 96 + lane + 64];
        float mx = fmaxf(v0, fmaxf(v1, v2));
#pragma unroll
        for (int o = 16; o >= 1; o >>= 1)
            mx = fmaxf(mx, __shfl_xor_sync(0xffffffffu, mx, o));
        float e0 = expf(v0 - mx), e1 = expf(v1 - mx), e2 = expf(v2 - mx);
        float sm = e0 + e1 + e2;
#pragma unroll
        for (int o = 16; o >= 1; o >>= 1)
            sm += __shfl_xor_sync(0xffffffffu, sm, o);
        float inv = 1.0f / sm;
        int rg = m0 + r;
        float ev[3] = {e0, e1, e2};
#pragma unroll
        for (int q = 0; q < 3; q++) {
            int c = lane + q * 32;
            float p = ev[q] * inv;
            bool isr = (c < KCLS);
            if (isr) g_probs[(size_t)rg * KCLS + c] = p;
            bool cond = isr && (p > SCORE_T);
            unsigned msk = __ballot_sync(0xffffffffu, cond);
            if (cond) {
                int leader = __ffs(msk) - 1;
                int rank = __popc(msk & ((1u << lane) - 1));
                int base = 0;
                if (lane == leader) base = atomicAdd(&g_count, __popc(msk));
                base = __shfl_sync(msk, base, leader);
                int pos = base + rank;
                if (pos < CAP) {
                    unsigned vb = __float_as_uint(p);
                    g_keys[pos] = ((ull)(~vb) << 32) | (unsigned)(rg * KCLS + c);
                }
            }
        }
    }
}

// --------- helper: fold one sorted list into sA (partner-min + merge) -------
__device__ __forceinline__ void fold_into(ull* sA, ull* sC,
                                          const ull* __restrict__ src) {
    int t = threadIdx.x;
    sC[t] = src[t]; sC[t + 1024] = src[t + 1024];
    __syncthreads();
#pragma unroll
    for (int q = 0; q < 2; q++) {
        int i = t + q * 1024;
        ull a = sA[i], c = sC[2047 - i];
        sA[i] = a < c ? a : c;
    }
    __syncthreads();
    for (int j = 1024; j > 0; j >>= 1) {
        int i = ((t & ~(j - 1)) << 1) | (t & (j - 1));
        ull a = sA[i], c = sA[i + j];
        if (a > c) { sA[i] = c; sA[i + j] = a; }
        __syncthreads();
    }
}

// ------ fused top-2048: sort chunks + 2 fold rounds in ONE kernel -----------
// 32 blocks (co-resident). Flag protocol: writer __threadfence + atomicExch;
// reader polls atomicAdd(flag,0), then __syncthreads. Folds exact (proven).
__global__ void __launch_bounds__(1024) k_topk() {
    __shared__ ull sA[2048], sC[2048];
    int t = threadIdx.x, b = blockIdx.x;
    int cnt = min(g_count, CAP);

    // ---- Phase 1: sort chunk b ----
    int base = b * 2048;
    if (base < cnt) {
        ull* src = g_keys + base;
        sA[t] = (base + t < cnt) ? src[t] : ~0ULL;
        sA[t + 1024] = (base + t + 1024 < cnt) ? src[t + 1024] : ~0ULL;
        __syncthreads();
        for (unsigned k = 2; k <= 2048; k <<= 1) {
            for (unsigned j = k >> 1; j > 0; j >>= 1) {
#pragma unroll
                for (int q = 0; q < 2; q++) {
                    unsigned i = t + q * 1024;
                    unsigned ixj = i ^ j;
                    if (ixj > i) {
                        bool up = ((i & k) == 0);
                        ull a = sA[i], c = sA[ixj];
                        if ((a > c) == up) { sA[i] = c; sA[ixj] = a; }
                    }
                }
                __syncthreads();
            }
        }
        src[t] = sA[t];
        src[t + 1024] = sA[t + 1024];
    }
    __syncthreads();
    if (t == 0) { __threadfence(); atomicExch(&g_flag1[b], 1u); }
    if (b >= 8) return;

    // ---- Phase 2: fold chunks 4b..4b+3 -> g_keys2 + b*2048 ----
    int c0 = 4 * b;
    bool act2 = ((size_t)c0 * 2048 < (size_t)cnt);
    if (act2) {
        int nact = 0;
        for (int i = 0; i < 4; i++)
            if ((size_t)(c0 + i) * 2048 < (size_t)cnt) nact = i + 1;
        if (t == 0)
            for (int i = 0; i < nact; i++)
                while (atomicAdd(&g_flag1[c0 + i], 0u) == 0u) {}
        __syncthreads();
        sA[t] = g_keys[(size_t)c0 * 2048 + t];
        sA[t + 1024] = g_keys[(size_t)c0 * 2048 + t + 1024];
        __syncthreads();
        for (int i = 1; i < nact; i++)
            fold_into(sA, sC, g_keys + (size_t)(c0 + i) * 2048);
        g_keys2[(size_t)b * 2048 + t] = sA[t];
        g_keys2[(size_t)b * 2048 + t + 1024] = sA[t + 1024];
    }
    __syncthreads();
    if (t == 0) { __threadfence(); atomicExch(&g_flag2[b], 1u); }
    if (b != 0) return;

    // ---- Phase 3: fold up to 8 lists from g_keys2 -> g_keys[0..2047] ----
    {
        int nact = 0;
        for (int i = 0; i < 8; i++)
            if ((size_t)i * 8192 < (size_t)cnt) nact = i + 1;
        if (t == 0)
            for (int i = 0; i < nact; i++)
                while (atomicAdd(&g_flag2[i], 0u) == 0u) {}
        __syncthreads();
        if (nact > 0) {
            sA[t] = g_keys2[t];
            sA[t + 1024] = g_keys2[t + 1024];
            __syncthreads();
            for (int i = 1; i < nact; i++)
                fold_into(sA, sC, g_keys2 + (size_t)i * 2048);
        } else {
            sA[t] = ~0ULL; sA[t + 1024] = ~0ULL;
            __syncthreads();
        }
        g_keys[t] = sA[t];
        g_keys[t + 1024] = sA[t + 1024];
    }
    // flags reset (all consumers done), downstream flag init, tail fill
    if (t < 32) g_flag1[t] = 0;
    if (t < 8) g_flag2[t] = 0;
    if (t < 64) { g_validw[t] = 0; g_rowNZ[t] = 0; }
    __syncthreads();
    if (t == 0 && cnt < MCAND) {
        int slot = cnt;
        for (int idx = 0; idx < NROWS * KCLS && slot < MCAND; idx++)
            if (!(g_probs[idx] > SCORE_T))
                g_keys[slot++] = (0xFFFFFFFFull << 32) | (unsigned)idx;
    }
}

// ---------------- bbox delta + decode + clip (warp per candidate) -----------
// Also appends candidate to its class bucket (order-irrelevant).
__global__ void __launch_bounds__(256) k_decode(
    const float* __restrict__ x, const float* __restrict__ bw,
    const float* __restrict__ bb, const float* __restrict__ props)
{
    int t = threadIdx.x, lane = t & 31, wid = t >> 5;
    int m = blockIdx.x * 8 + wid;
    ull key = g_keys[m];               // final list lives in g_keys
    unsigned hi = (unsigned)(key >> 32);
    unsigned idx = (unsigned)key;
    if (idx >= (unsigned)(NROWS * KCLS)) idx = 0;   // defensive
    float score = (hi == 0xFFFFFFFFu) ? -1.0f : __uint_as_float(~hi);
    int prop = idx / KCLS, cls = idx - prop * KCLS;

    const float4* x4 = (const float4*)(x + (size_t)prop * DDIM);
    const float4* wr = (const float4*)bw;   // [k][80] float4s
    float a0 = 0, a1 = 0, a2 = 0, a3 = 0;
#pragma unroll 4
    for (int k = lane; k < DDIM / 4; k += 32) {
        float4 xv = __ldg(x4 + k);
        float4 w0 = __ldg(wr + (size_t)(4 * k + 0) * KCLS + cls);
        float4 w1 = __ldg(wr + (size_t)(4 * k + 1) * KCLS + cls);
        float4 w2 = __ldg(wr + (size_t)(4 * k + 2) * KCLS + cls);
        float4 w3 = __ldg(wr + (size_t)(4 * k + 3) * KCLS + cls);
        a0 = fmaf(xv.x, w0.x, fmaf(xv.y, w1.x, fmaf(xv.z, w2.x, fmaf(xv.w, w3.x, a0))));
        a1 = fmaf(xv.x, w0.y, fmaf(xv.y, w1.y, fmaf(xv.z, w2.y, fmaf(xv.w, w3.y, a1))));
        a2 = fmaf(xv.x, w0.z, fmaf(xv.y, w1.z, fmaf(xv.z, w2.z, fmaf(xv.w, w3.z, a2))));
        a3 = fmaf(xv.x, w0.w, fmaf(xv.y, w1.w, fmaf(xv.z, w2.w, fmaf(xv.w, w3.w, a3))));
    }
#pragma unroll
    for (int o = 16; o >= 1; o >>= 1) {
        a0 += __shfl_xor_sync(0xffffffffu, a0, o);
        a1 += __shfl_xor_sync(0xffffffffu, a1, o);
        a2 += __shfl_xor_sync(0xffffffffu, a2, o);
        a3 += __shfl_xor_sync(0xffffffffu, a3, o);
    }
    if (lane == 0) {
        float d0 = a0 + bb[cls * 4 + 0], d1 = a1 + bb[cls * 4 + 1];
        float d2 = a2 + bb[cls * 4 + 2], d3 = a3 + bb[cls * 4 + 3];
        float px1 = props[prop * 4 + 0], py1 = props[prop * 4 + 1];
        float px2 = props[prop * 4 + 2], py2 = props[prop * 4 + 3];
        float w = px2 - px1, h = py2 - py1;
        float cx = px1 + 0.5f * w, cy = py1 + 0.5f * h;
        float dx = d0 / 10.0f, dy = d1 / 10.0f;
        float dw = fminf(d2 / 5.0f, SCALE_CLAMP), dh = fminf(d3 / 5.0f, SCALE_CLAMP);
        float pcx = dx * w + cx, pcy = dy * h + cy;
        float pw = expf(dw) * w, ph = expf(dh) * h;
        float x1 = pcx - 0.5f * pw, y1 = pcy - 0.5f * ph;
        float x2 = pcx + 0.5f * pw, y2 = pcy + 0.5f * ph;
        x1 = fminf(fmaxf(x1, 0.f), IMG_W); y1 = fminf(fmaxf(y1, 0.f), IMG_H);
        x2 = fminf(fmaxf(x2, 0.f), IMG_W); y2 = fminf(fmaxf(y2, 0.f), IMG_H);
        g_box[m] = make_float4(x1, y1, x2, y2);
        g_cls[m] = cls;
        g_score[m] = score;
        if (score > SCORE_T) atomicOr(&g_validw[m >> 5], 1u << (m & 31));
        int slot = atomicAdd(&g_clsCnt[cls], 1);
        g_bucket[cls * MCAND + slot] = m;
    }
}

// ----------- suppression mask via class buckets (warp per row) --------------
// bit(r,j) = (j>r) && same class && IoU>NMS_T — identical to before, but only
// the ~cnt/KCLS same-class candidates are visited per row (80x less work).
__global__ void __launch_bounds__(512) k_mask() {
    __shared__ unsigned smask[16][64];
    int t = threadIdx.x;
    int wid = t >> 5, lane = t & 31;
    int r = blockIdx.x * 16 + wid;
    smask[wid][lane] = 0;
    smask[wid][lane + 32] = 0;
    __syncwarp();
    bool validr = (g_validw[r >> 5] >> (r & 31)) & 1u;
    unsigned anyw = 0;
    if (validr) {
        float4 rb = g_box[r];
        int rc = g_cls[r];
        float ra = (rb.z - rb.x) * (rb.w - rb.y);
        int n = g_clsCnt[rc];
        const int* bucket = g_bucket + rc * MCAND;
        for (int i0 = 0; i0 < n; i0 += 32) {
            int i = i0 + lane;
            bool bit = false;
            int j = 0;
            if (i < n) {
                j = bucket[i];
                if (j > r) {
                    float4 jb = g_box[j];
                    float xx1 = fmaxf(rb.x, jb.x), yy1 = fmaxf(rb.y, jb.y);
                    float xx2 = fminf(rb.z, jb.z), yy2 = fminf(rb.w, jb.w);
                    float inter = fmaxf(xx2 - xx1, 0.f) * fmaxf(yy2 - yy1, 0.f);
                    float ja = (jb.z - jb.x) * (jb.w - jb.y);
                    float iou = inter / fmaxf(ra + ja - inter, 1e-9f);
                    bit = iou > NMS_T;
                }
            }
            if (bit) atomicOr(&smask[wid][j >> 5], 1u << (j & 31));
            anyw |= __ballot_sync(0xffffffffu, bit);
        }
    }
    __syncwarp();
    g_mask[(size_t)r * 64 + lane] = smask[wid][lane];
    g_mask[(size_t)r * 64 + lane + 32] = smask[wid][lane + 32];
    if (lane == 0 && anyw) atomicOr(&g_rowNZ[r >> 5], 1u << (r & 31));
}

// --------- NMS via Jacobi fixpoint (exact: mask is strictly triangular) -----
__global__ void __launch_bounds__(1024) k_nms_out(float* __restrict__ out) {
    __shared__ unsigned Rcur[64], contrib[64], sval[64], nzw[64];
    __shared__ unsigned racc[16][64];
    __shared__ int s_changed;
    __shared__ int kscan[65];
    __shared__ int fidx[NTOPK];
    int t = threadIdx.x;
    if (t == 0) g_count = 0;           // reset for next replay (after last use)
    if (t < KCLS) g_clsCnt[t] = 0;     // reset class buckets for next replay
    if (t < 64) { Rcur[t] = 0; sval[t] = g_validw[t]; nzw[t] = g_rowNZ[t]; }
    __syncthreads();
    int w = t & 63, g = t >> 6;
    unsigned gm = (0x00010001u << g);
    for (int iter = 0; iter < MCAND; iter++) {
        if (t < 64) contrib[t] = sval[t] & ~Rcur[t] & nzw[t];
        if (t == 0) s_changed = 0;
        __syncthreads();
        unsigned acc = 0;
        for (int rw = 0; rw < 64; rw++) {
            unsigned bits = contrib[rw] & gm;
            while (bits) {
                int b = __ffs(bits) - 1; bits &= bits - 1;
                acc |= g_mask[(size_t)(rw * 32 + b) * 64 + w];
            }
        }
        racc[g][w] = acc;
        __syncthreads();
        if (t < 64) {
            unsigned a = 0;
#pragma unroll
            for (int q = 0; q < 16; q++) a |= racc[q][t];
            if (a != Rcur[t]) s_changed = 1;
            Rcur[t] = a;
        }
        __syncthreads();
        if (!s_changed) break;
    }
    if (t < 64) sval[t] = sval[t] & ~Rcur[t];
    __syncthreads();
    if (t == 0) {
        int run = 0;
        for (int ww = 0; ww < 64; ww++) { kscan[ww] = run; run += __popc(sval[ww]); }
        kscan[64] = run;
    }
    __syncthreads();
    int KC = kscan[64];
    for (int i = t; i < MCAND; i += 1024) {
        int ww = i >> 5, b = i & 31;
        unsigned kw = sval[ww];
        bool kp = (kw >> b) & 1u;
        int kr = kscan[ww] + __popc(kw & ((1u << b) - 1));
        int slot = kp ? kr : (KC + i - kr);
        if (slot < NTOPK) fidx[slot] = i;
    }
    __syncthreads();
    if (t < NTOPK) {
        int i = fidx[t];
        bool kp = (sval[i >> 5] >> (i & 31)) & 1u;
        float4 b4 = g_box[i];
        out[t * 4 + 0] = b4.x;
        out[t * 4 + 1] = b4.y;
        out[t * 4 + 2] = b4.z;
        out[t * 4 + 3] = b4.w;
        out[400 + t] = kp ? g_score[i] : -1.0f;
        out[500 + t] = (float)g_cls[i];
        out[600 + t] = kp ? 1.0f : 0.0f;
    }
}

// ---------------- launch ----------------------------------------------------
extern "C" void kernel_launch(void* const* d_in, const int* in_sizes, int n_in,
                              void* d_out, int out_size) {
    (void)in_sizes; (void)n_in; (void)out_size;
    const float* x     = (const float*)d_in[0];
    const float* cw    = (const float*)d_in[1];
    const float* cb    = (const float*)d_in[2];
    const float* bw    = (const float*)d_in[3];
    const float* bb    = (const float*)d_in[4];
    const float* props = (const float*)d_in[5];
    float* out = (float*)d_out;

    k_gemm_softmax<<<NROWS / BM, 384>>>(x, cw, cb);
    k_topk<<<32, 1024>>>();            // fused sort + 2 fold rounds
    k_decode<<<MCAND / 8, 256>>>(x, bw, bb, props);
    k_mask<<<MCAND / 16, 512>>>();
    k_nms_out<<<1, 1024>>>(out);
}